// round 14
// baseline (speedup 1.0000x reference)
#include <cuda_runtime.h>
#include <cuda_fp16.h>
#include <cstdint>

// ---------------- problem constants ----------------
#define TOKENS 8192
#define INF    4096
#define OUTF   4096

// ---------------- GEMM tiling (R4 winner config) ----------------
#define BM 256
#define BN 128
#define BK 64
#define STAGES 4
#define KITERS (INF / BK)                  // 64
#define A_BYTES (BM * BK * 2)              // 32 KB
#define B_BYTES (BN * BK * 2)              // 16 KB
#define STAGE_BYTES (A_BYTES + B_BYTES)    // 48 KB
#define SMEM_DYN (STAGES * STAGE_BYTES + 1024)   // ~193 KB
#define NTILES ((TOKENS / BM) * (OUTF / BN))     // 1024

// ---------------- device scratch (statics, no allocs) ----------------
// NOTE: g_tag is zero at module load AND re-zeroed by build_w every call
// (self-cleaning pipeline) -> no separate zeroing kernel needed.
static __device__ __half g_x16[(size_t)TOKENS * INF];  // 64 MB
static __device__ __half g_w16[(size_t)OUTF * INF];    // 32 MB
static __device__ int    g_tag[(size_t)OUTF * INF];    // 64 MB
static __device__ unsigned g_ticket;

// ---------------- helpers ----------------
__device__ __forceinline__ uint32_t smem_u32(const void* p) {
    uint32_t a;
    asm("{ .reg .u64 t; cvta.to.shared.u64 t, %1; cvt.u32.u64 %0, t; }"
        : "=r"(a) : "l"(p));
    return a;
}

#define SWZ(o) ((o) ^ (((o) >> 3) & 0x70))

__device__ __forceinline__ void cp_async16(uint32_t saddr, const void* gptr) {
    uint64_t g = __cvta_generic_to_global((void*)gptr);
    asm volatile("cp.async.cg.shared.global [%0], [%1], 16;" :: "r"(saddr), "l"(g) : "memory");
}
#define CP_COMMIT() asm volatile("cp.async.commit_group;" ::: "memory")
#define CP_WAIT(n)  asm volatile("cp.async.wait_group %0;" :: "n"(n) : "memory")

__device__ __forceinline__ void ldsm_x4(uint32_t (&r)[4], uint32_t addr) {
    asm volatile("ldmatrix.sync.aligned.m8n8.x4.shared.b16 {%0,%1,%2,%3}, [%4];"
                 : "=r"(r[0]), "=r"(r[1]), "=r"(r[2]), "=r"(r[3]) : "r"(addr));
}

__device__ __forceinline__ void mma16816(float (&d)[4], const uint32_t (&a)[4],
                                         uint32_t b0, uint32_t b1) {
    asm volatile(
        "mma.sync.aligned.m16n8k16.row.col.f32.f16.f16.f32 "
        "{%0,%1,%2,%3}, {%4,%5,%6,%7}, {%8,%9}, {%0,%1,%2,%3};"
        : "+f"(d[0]), "+f"(d[1]), "+f"(d[2]), "+f"(d[3])
        : "r"(a[0]), "r"(a[1]), "r"(a[2]), "r"(a[3]), "r"(b0), "r"(b1));
}

__device__ __forceinline__ void stcs_f2(float* p, float x, float y) {
    asm volatile("st.global.cs.v2.f32 [%0], {%1, %2};"
                 :: "l"(p), "f"(x), "f"(y) : "memory");
}

__device__ __forceinline__ void stcs_u4(uint4* p, uint4 v) {
    asm volatile("st.global.cs.v4.b32 [%0], {%1, %2, %3, %4};"
                 :: "l"(p), "r"(v.x), "r"(v.y), "r"(v.z), "r"(v.w) : "memory");
}

__device__ __forceinline__ uint4 ldcs_u4(const uint4* p) {
    uint4 v;
    asm volatile("ld.global.cs.v4.b32 {%0, %1, %2, %3}, [%4];"
                 : "=r"(v.x), "=r"(v.y), "=r"(v.z), "=r"(v.w) : "l"(p));
    return v;
}

// ---------------- prep kernels ----------------
// K1: fire-and-forget winner-tag atomics (latency-bound) overlapped with
//     the DRAM-bound x -> fp16 convert. Also resets the GEMM ticket.
__global__ void scatter_cvt(const int* __restrict__ ridx, const int* __restrict__ cidx,
                            const float* __restrict__ x, int nnz) {
    if (blockIdx.x == 0 && threadIdx.x == 0) g_ticket = 0u;
    const size_t stride = (size_t)gridDim.x * blockDim.x;
    const size_t gid = (size_t)blockIdx.x * blockDim.x + threadIdx.x;

    for (size_t i = gid; i < (size_t)nnz; i += stride) {
        size_t pos = (size_t)__ldg(ridx + i) * INF + __ldg(cidx + i);
        atomicMax(&g_tag[pos], (int)i + 1);
    }

    const float4* xv = reinterpret_cast<const float4*>(x);
    __half2* xo = reinterpret_cast<__half2*>(g_x16);
    for (size_t j = gid; j < (size_t)TOKENS * INF / 4; j += stride) {
        float4 v = __ldg(&xv[j]);
        xo[2 * j + 0] = __floats2half2_rn(v.x, v.y);
        xo[2 * j + 1] = __floats2half2_rn(v.z, v.w);
    }
}

// K2: dense W build — coalesced streaming. Reads tags, writes w16, and
//     ZEROES the tags behind itself (self-cleaning: next call sees tag==0).
__global__ void build_w(const float* __restrict__ w) {
    size_t stride = (size_t)gridDim.x * blockDim.x;
    size_t nblk = (size_t)OUTF * INF / 8;          // 2M groups of 8
    const uint4* tv = reinterpret_cast<const uint4*>(g_tag);
    uint4* tz = reinterpret_cast<uint4*>(g_tag);
    uint4* wv = reinterpret_cast<uint4*>(g_w16);
    const uint4 z = {0u, 0u, 0u, 0u};
    for (size_t j = (size_t)blockIdx.x * blockDim.x + threadIdx.x; j < nblk; j += stride) {
        uint4 t0 = ldcs_u4(&tv[2 * j + 0]);
        uint4 t1 = ldcs_u4(&tv[2 * j + 1]);
        int tg[8] = {(int)t0.x, (int)t0.y, (int)t0.z, (int)t0.w,
                     (int)t1.x, (int)t1.y, (int)t1.z, (int)t1.w};
        __half h[8];
        #pragma unroll
        for (int e = 0; e < 8; ++e)
            h[e] = tg[e] ? __float2half_rn(__ldg(w + (tg[e] - 1))) : __half(0.f);
        uint4 o;
        o.x = ((uint32_t)__half_as_ushort(h[1]) << 16) | __half_as_ushort(h[0]);
        o.y = ((uint32_t)__half_as_ushort(h[3]) << 16) | __half_as_ushort(h[2]);
        o.z = ((uint32_t)__half_as_ushort(h[5]) << 16) | __half_as_ushort(h[4]);
        o.w = ((uint32_t)__half_as_ushort(h[7]) << 16) | __half_as_ushort(h[6]);
        wv[j] = o;                      // GEMM reads w16 soon: keep in L2
        stcs_u4(&tz[2 * j + 0], z);     // reset tags for next call (.cs, L2-clean)
        stcs_u4(&tz[2 * j + 1], z);
    }
}

// ---------------- GEMM fill helpers (R4) ----------------
__device__ __forceinline__ void fill_full(uint32_t sbase, int stage, int kblk,
                                          const __half* Ab, const __half* Bb, int tid) {
    const int k0 = kblk * BK;
    uint32_t sa = sbase + stage * STAGE_BYTES;
    #pragma unroll
    for (int j = 0; j < 8; ++j) {
        int q = tid + j * 256; int r = q >> 3, cb = (q & 7) * 16;
        cp_async16(sa + SWZ(r * 128 + cb), Ab + (size_t)r * INF + k0 + (q & 7) * 8);
    }
    uint32_t sb = sa + A_BYTES;
    #pragma unroll
    for (int j = 0; j < 4; ++j) {
        int q = tid + j * 256; int r = q >> 3, cb = (q & 7) * 16;
        cp_async16(sb + SWZ(r * 128 + cb), Bb + (size_t)r * INF + k0 + (q & 7) * 8);
    }
}

__device__ __forceinline__ void fill_part(uint32_t sbase, int stage, int kblk, int part,
                                          const __half* Ab, const __half* Bb, int tid) {
    const int k0 = kblk * BK;
    uint32_t sa = sbase + stage * STAGE_BYTES;
    #pragma unroll
    for (int jj = 0; jj < 2; ++jj) {
        int q = tid + (2 * part + jj) * 256; int r = q >> 3, cb = (q & 7) * 16;
        cp_async16(sa + SWZ(r * 128 + cb), Ab + (size_t)r * INF + k0 + (q & 7) * 8);
    }
    {
        int q = tid + part * 256; int r = q >> 3, cb = (q & 7) * 16;
        cp_async16(sa + A_BYTES + SWZ(r * 128 + cb), Bb + (size_t)r * INF + k0 + (q & 7) * 8);
    }
}

// ---------------- GEMM: out[m,n] = sum_k x16[m,k]*w16[n,k] + bias[n] (R4 core) ----------------
__global__ void __launch_bounds__(256)
gemm_kernel(const float* __restrict__ bias, float* __restrict__ out) {
    extern __shared__ char smem_raw[];
    __shared__ int s_tile;
    uint32_t sbase = (smem_u32(smem_raw) + 1023u) & ~1023u;

    const int tid  = threadIdx.x;
    const int lane = tid & 31;
    const int wid  = tid >> 5;
    const int warp_m = wid & 3;   // 0..3 -> 64 rows each
    const int warp_n = wid >> 2;  // 0..1 -> 64 cols each

    const int a_row_l = ((lane >> 3) & 1) * 8 + (lane & 7);
    const int a_koff  = ((lane >> 4) & 1) * 8;
    const int b_row_l = ((lane >> 4) & 1) * 8 + (lane & 7);
    const int b_koff  = ((lane >> 3) & 1) * 8;

    float acc[4][8][4];
    #pragma unroll
    for (int i = 0; i < 4; ++i)
        #pragma unroll
        for (int j = 0; j < 8; ++j)
            #pragma unroll
            for (int k = 0; k < 4; ++k) acc[i][j][k] = 0.f;

    auto map_tile = [](int tt, const __half*& A, const __half*& B, int& m, int& n) {
        // groups of 8 bn x 32 bm = 256 tiles -> B panel (8 MB) stays L2-resident
        int grp = tt >> 8, idx = tt & 255;
        m = idx & 31;
        n = (grp << 3) | (idx >> 5);
        A = g_x16 + (size_t)m * BM * INF;
        B = g_w16 + (size_t)n * BN * INF;
    };

    if (tid == 0) s_tile = (int)atomicAdd(&g_ticket, 1u);
    __syncthreads();
    int t = s_tile;
    if (t >= NTILES) return;

    int bm, bn;
    const __half *Ab, *Bb;
    map_tile(t, Ab, Bb, bm, bn);

    fill_full(sbase, 0, 0, Ab, Bb, tid); CP_COMMIT();
    fill_full(sbase, 1, 1, Ab, Bb, tid); CP_COMMIT();
    fill_full(sbase, 2, 2, Ab, Bb, tid); CP_COMMIT();

    while (true) {
        if (tid == 0) s_tile = (int)atomicAdd(&g_ticket, 1u);

        for (int c = 0; c < KITERS; ++c) {
            CP_WAIT(2);
            __syncthreads();

            const int sc = c & (STAGES - 1);
            uint32_t sa = sbase + sc * STAGE_BYTES;
            uint32_t sb = sa + A_BYTES;
            const bool do_fill = (c < KITERS - 3);
            const int  nstage  = (c + 3) & (STAGES - 1);

            #pragma unroll
            for (int ks = 0; ks < BK / 16; ++ks) {
                if (do_fill) fill_part(sbase, nstage, c + 3, ks, Ab, Bb, tid);

                uint32_t afr[4][4];
                #pragma unroll
                for (int mt = 0; mt < 4; ++mt) {
                    int row = warp_m * 64 + mt * 16 + a_row_l;
                    int col = ks * 16 + a_koff;
                    ldsm_x4(afr[mt], sa + SWZ(row * 128 + col * 2));
                }
                uint32_t bfr[4][4];
                #pragma unroll
                for (int h = 0; h < 4; ++h) {
                    int row = warp_n * 64 + h * 16 + b_row_l;
                    int col = ks * 16 + b_koff;
                    ldsm_x4(bfr[h], sb + SWZ(row * 128 + col * 2));
                }
                #pragma unroll
                for (int mt = 0; mt < 4; ++mt)
                    #pragma unroll
                    for (int nt = 0; nt < 8; ++nt)
                        mma16816(acc[mt][nt], afr[mt],
                                 bfr[nt >> 1][(nt & 1) * 2], bfr[nt >> 1][(nt & 1) * 2 + 1]);
            }
            CP_COMMIT();
        }

        __syncthreads();                 // compute done; s_tile visible
        const int tn = s_tile;

        int bm2 = 0, bn2 = 0;
        const __half *Ab2 = nullptr, *Bb2 = nullptr;
        if (tn < NTILES) {
            map_tile(tn, Ab2, Bb2, bm2, bn2);
            fill_full(sbase, 0, 0, Ab2, Bb2, tid); CP_COMMIT();
            fill_full(sbase, 1, 1, Ab2, Bb2, tid); CP_COMMIT();
            fill_full(sbase, 2, 2, Ab2, Bb2, tid); CP_COMMIT();
        }

        {
            const int gr = lane >> 2;
            const int gc = (lane & 3) * 2;
            #pragma unroll
            for (int mt = 0; mt < 4; ++mt) {
                int row0 = bm * BM + warp_m * 64 + mt * 16 + gr;
                #pragma unroll
                for (int nt = 0; nt < 8; ++nt) {
                    int col = bn * BN + warp_n * 64 + nt * 8 + gc;
                    float2 b2 = *reinterpret_cast<const float2*>(bias + col);
                    stcs_f2(out + (size_t)row0 * OUTF + col,
                            acc[mt][nt][0] + b2.x, acc[mt][nt][1] + b2.y);
                    stcs_f2(out + (size_t)(row0 + 8) * OUTF + col,
                            acc[mt][nt][2] + b2.x, acc[mt][nt][3] + b2.y);
                    acc[mt][nt][0] = 0.f; acc[mt][nt][1] = 0.f;
                    acc[mt][nt][2] = 0.f; acc[mt][nt][3] = 0.f;
                }
            }
        }

        if (tn >= NTILES) break;
        t = tn; bm = bm2; bn = bn2; Ab = Ab2; Bb = Bb2;
    }
}

// ---------------- launch ----------------
extern "C" void kernel_launch(void* const* d_in, const int* in_sizes, int n_in,
                              void* d_out, int out_size) {
    const float* x    = (const float*)d_in[0];
    const float* w    = (const float*)d_in[1];
    const float* bias = (const float*)d_in[2];
    const int*   ridx = (const int*)d_in[3];
    const int*   cidx = (const int*)d_in[4];
    float* out = (float*)d_out;
    const int nnz = in_sizes[1];

    cudaFuncSetAttribute(gemm_kernel, cudaFuncAttributeMaxDynamicSharedMemorySize, SMEM_DYN);

    scatter_cvt<<<2048, 256>>>(ridx, cidx, x, nnz);
    build_w<<<2048, 256>>>(w);

    gemm_kernel<<<160, 256, SMEM_DYN>>>(bias, out);
}

// round 16
// speedup vs baseline: 1.0114x; 1.0114x over previous
#include <cuda_runtime.h>
#include <cuda_fp16.h>
#include <cstdint>

// ---------------- problem constants ----------------
#define TOKENS 8192
#define INF    4096
#define OUTF   4096

// ---------------- GEMM tiling (R4 winner config) ----------------
#define BM 256
#define BN 128
#define BK 64
#define STAGES 4
#define KITERS (INF / BK)                  // 64
#define A_BYTES (BM * BK * 2)              // 32 KB
#define B_BYTES (BN * BK * 2)              // 16 KB
#define STAGE_BYTES (A_BYTES + B_BYTES)    // 48 KB
#define SMEM_DYN (STAGES * STAGE_BYTES + 1024)   // ~193 KB
#define NTILES ((TOKENS / BM) * (OUTF / BN))     // 1024

// ---------------- device scratch (statics, no allocs) ----------------
static __device__ __half g_x16[(size_t)TOKENS * INF];  // 64 MB
static __device__ __half g_w16[(size_t)OUTF * INF];    // 32 MB
static __device__ int    g_tag[(size_t)OUTF * INF];    // 64 MB
static __device__ unsigned g_ticket;

// ---------------- helpers ----------------
__device__ __forceinline__ uint32_t smem_u32(const void* p) {
    uint32_t a;
    asm("{ .reg .u64 t; cvta.to.shared.u64 t, %1; cvt.u32.u64 %0, t; }"
        : "=r"(a) : "l"(p));
    return a;
}

#define SWZ(o) ((o) ^ (((o) >> 3) & 0x70))

__device__ __forceinline__ uint32_t h2_bits(__half2 h) {
    return *reinterpret_cast<uint32_t*>(&h);
}

__device__ __forceinline__ void cp_async16(uint32_t saddr, const void* gptr) {
    uint64_t g = __cvta_generic_to_global((void*)gptr);
    asm volatile("cp.async.cg.shared.global [%0], [%1], 16;" :: "r"(saddr), "l"(g) : "memory");
}
#define CP_COMMIT() asm volatile("cp.async.commit_group;" ::: "memory")
#define CP_WAIT(n)  asm volatile("cp.async.wait_group %0;" :: "n"(n) : "memory")

__device__ __forceinline__ void ldsm_x4(uint32_t (&r)[4], uint32_t addr) {
    asm volatile("ldmatrix.sync.aligned.m8n8.x4.shared.b16 {%0,%1,%2,%3}, [%4];"
                 : "=r"(r[0]), "=r"(r[1]), "=r"(r[2]), "=r"(r[3]) : "r"(addr));
}

__device__ __forceinline__ void mma16816(float (&d)[4], const uint32_t (&a)[4],
                                         uint32_t b0, uint32_t b1) {
    asm volatile(
        "mma.sync.aligned.m16n8k16.row.col.f32.f16.f16.f32 "
        "{%0,%1,%2,%3}, {%4,%5,%6,%7}, {%8,%9}, {%0,%1,%2,%3};"
        : "+f"(d[0]), "+f"(d[1]), "+f"(d[2]), "+f"(d[3])
        : "r"(a[0]), "r"(a[1]), "r"(a[2]), "r"(a[3]), "r"(b0), "r"(b1));
}

__device__ __forceinline__ void stcs_f2(float* p, float x, float y) {
    asm volatile("st.global.cs.v2.f32 [%0], {%1, %2};"
                 :: "l"(p), "f"(x), "f"(y) : "memory");
}

__device__ __forceinline__ void stcs_u4(uint4* p, uint4 v) {
    asm volatile("st.global.cs.v4.b32 [%0], {%1, %2, %3, %4};"
                 :: "l"(p), "r"(v.x), "r"(v.y), "r"(v.z), "r"(v.w) : "memory");
}

__device__ __forceinline__ uint4 ldcs_u4(const uint4* p) {
    uint4 v;
    asm volatile("ld.global.cs.v4.b32 {%0, %1, %2, %3}, [%4];"
                 : "=r"(v.x), "=r"(v.y), "=r"(v.z), "=r"(v.w) : "l"(p));
    return v;
}

// ---------------- prep kernels ----------------
// K1: zero tag (streaming .cs), reset ticket
__global__ void zero_tag() {
    if (blockIdx.x == 0 && threadIdx.x == 0) g_ticket = 0u;
    size_t stride = (size_t)gridDim.x * blockDim.x;
    uint4 z = {0u, 0u, 0u, 0u};
    uint4* t = reinterpret_cast<uint4*>(g_tag);
    for (size_t j = (size_t)blockIdx.x * blockDim.x + threadIdx.x;
         j < (size_t)OUTF * INF / 4; j += stride)
        stcs_u4(&t[j], z);
}

// K2: fire-and-forget winner-tag atomics overlapped with x -> fp16 convert.
// x16 output stored .cs (single write, read much later -> don't claim L2).
__global__ void scatter_cvt(const int* __restrict__ ridx, const int* __restrict__ cidx,
                            const float* __restrict__ x, int nnz) {
    const size_t stride = (size_t)gridDim.x * blockDim.x;
    const size_t gid = (size_t)blockIdx.x * blockDim.x + threadIdx.x;

    for (size_t i = gid; i < (size_t)nnz; i += stride) {
        size_t pos = (size_t)__ldg(ridx + i) * INF + __ldg(cidx + i);
        atomicMax(&g_tag[pos], (int)i + 1);
    }

    const float4* xv = reinterpret_cast<const float4*>(x);
    uint4* xo = reinterpret_cast<uint4*>(g_x16);
    for (size_t j = gid; j < (size_t)TOKENS * INF / 8; j += stride) {
        float4 v0 = __ldg(&xv[2 * j + 0]);
        float4 v1 = __ldg(&xv[2 * j + 1]);
        uint4 o;
        o.x = h2_bits(__floats2half2_rn(v0.x, v0.y));
        o.y = h2_bits(__floats2half2_rn(v0.z, v0.w));
        o.z = h2_bits(__floats2half2_rn(v1.x, v1.y));
        o.w = h2_bits(__floats2half2_rn(v1.z, v1.w));
        stcs_u4(&xo[j], o);
    }
}

// K3: dense W build — coalesced streaming; tag reads single-use (.cs)
__global__ void build_w(const float* __restrict__ w) {
    size_t stride = (size_t)gridDim.x * blockDim.x;
    size_t nblk = (size_t)OUTF * INF / 8;          // 2M groups of 8
    const uint4* tv = reinterpret_cast<const uint4*>(g_tag);
    uint4* wv = reinterpret_cast<uint4*>(g_w16);
    for (size_t j = (size_t)blockIdx.x * blockDim.x + threadIdx.x; j < nblk; j += stride) {
        uint4 t0 = ldcs_u4(&tv[2 * j + 0]);
        uint4 t1 = ldcs_u4(&tv[2 * j + 1]);
        int tg[8] = {(int)t0.x, (int)t0.y, (int)t0.z, (int)t0.w,
                     (int)t1.x, (int)t1.y, (int)t1.z, (int)t1.w};
        __half h[8];
        #pragma unroll
        for (int e = 0; e < 8; ++e)
            h[e] = tg[e] ? __float2half_rn(__ldg(w + (tg[e] - 1))) : __half(0.f);
        uint4 o;
        o.x = ((uint32_t)__half_as_ushort(h[1]) << 16) | __half_as_ushort(h[0]);
        o.y = ((uint32_t)__half_as_ushort(h[3]) << 16) | __half_as_ushort(h[2]);
        o.z = ((uint32_t)__half_as_ushort(h[5]) << 16) | __half_as_ushort(h[4]);
        o.w = ((uint32_t)__half_as_ushort(h[7]) << 16) | __half_as_ushort(h[6]);
        wv[j] = o;   // normal store: GEMM reads w16 soon, keep in L2
    }
}

// ---------------- GEMM fill helpers (R4) ----------------
__device__ __forceinline__ void fill_full(uint32_t sbase, int stage, int kblk,
                                          const __half* Ab, const __half* Bb, int tid) {
    const int k0 = kblk * BK;
    uint32_t sa = sbase + stage * STAGE_BYTES;
    #pragma unroll
    for (int j = 0; j < 8; ++j) {
        int q = tid + j * 256; int r = q >> 3, cb = (q & 7) * 16;
        cp_async16(sa + SWZ(r * 128 + cb), Ab + (size_t)r * INF + k0 + (q & 7) * 8);
    }
    uint32_t sb = sa + A_BYTES;
    #pragma unroll
    for (int j = 0; j < 4; ++j) {
        int q = tid + j * 256; int r = q >> 3, cb = (q & 7) * 16;
        cp_async16(sb + SWZ(r * 128 + cb), Bb + (size_t)r * INF + k0 + (q & 7) * 8);
    }
}

__device__ __forceinline__ void fill_part(uint32_t sbase, int stage, int kblk, int part,
                                          const __half* Ab, const __half* Bb, int tid) {
    const int k0 = kblk * BK;
    uint32_t sa = sbase + stage * STAGE_BYTES;
    #pragma unroll
    for (int jj = 0; jj < 2; ++jj) {
        int q = tid + (2 * part + jj) * 256; int r = q >> 3, cb = (q & 7) * 16;
        cp_async16(sa + SWZ(r * 128 + cb), Ab + (size_t)r * INF + k0 + (q & 7) * 8);
    }
    {
        int q = tid + part * 256; int r = q >> 3, cb = (q & 7) * 16;
        cp_async16(sa + A_BYTES + SWZ(r * 128 + cb), Bb + (size_t)r * INF + k0 + (q & 7) * 8);
    }
}

// ---------------- GEMM: out[m,n] = sum_k x16[m,k]*w16[n,k] + bias[n] (R4 core) ----------------
__global__ void __launch_bounds__(256)
gemm_kernel(const float* __restrict__ bias, float* __restrict__ out) {
    extern __shared__ char smem_raw[];
    __shared__ int s_tile;
    uint32_t sbase = (smem_u32(smem_raw) + 1023u) & ~1023u;

    const int tid  = threadIdx.x;
    const int lane = tid & 31;
    const int wid  = tid >> 5;
    const int warp_m = wid & 3;   // 0..3 -> 64 rows each
    const int warp_n = wid >> 2;  // 0..1 -> 64 cols each

    const int a_row_l = ((lane >> 3) & 1) * 8 + (lane & 7);
    const int a_koff  = ((lane >> 4) & 1) * 8;
    const int b_row_l = ((lane >> 4) & 1) * 8 + (lane & 7);
    const int b_koff  = ((lane >> 3) & 1) * 8;

    float acc[4][8][4];
    #pragma unroll
    for (int i = 0; i < 4; ++i)
        #pragma unroll
        for (int j = 0; j < 8; ++j)
            #pragma unroll
            for (int k = 0; k < 4; ++k) acc[i][j][k] = 0.f;

    auto map_tile = [](int tt, const __half*& A, const __half*& B, int& m, int& n) {
        // groups of 8 bn x 32 bm = 256 tiles -> B panel (8 MB) stays L2-resident
        int grp = tt >> 8, idx = tt & 255;
        m = idx & 31;
        n = (grp << 3) | (idx >> 5);
        A = g_x16 + (size_t)m * BM * INF;
        B = g_w16 + (size_t)n * BN * INF;
    };

    if (tid == 0) s_tile = (int)atomicAdd(&g_ticket, 1u);
    __syncthreads();
    int t = s_tile;
    if (t >= NTILES) return;

    int bm, bn;
    const __half *Ab, *Bb;
    map_tile(t, Ab, Bb, bm, bn);

    fill_full(sbase, 0, 0, Ab, Bb, tid); CP_COMMIT();
    fill_full(sbase, 1, 1, Ab, Bb, tid); CP_COMMIT();
    fill_full(sbase, 2, 2, Ab, Bb, tid); CP_COMMIT();

    while (true) {
        if (tid == 0) s_tile = (int)atomicAdd(&g_ticket, 1u);

        for (int c = 0; c < KITERS; ++c) {
            CP_WAIT(2);
            __syncthreads();

            const int sc = c & (STAGES - 1);
            uint32_t sa = sbase + sc * STAGE_BYTES;
            uint32_t sb = sa + A_BYTES;
            const bool do_fill = (c < KITERS - 3);
            const int  nstage  = (c + 3) & (STAGES - 1);

            #pragma unroll
            for (int ks = 0; ks < BK / 16; ++ks) {
                if (do_fill) fill_part(sbase, nstage, c + 3, ks, Ab, Bb, tid);

                uint32_t afr[4][4];
                #pragma unroll
                for (int mt = 0; mt < 4; ++mt) {
                    int row = warp_m * 64 + mt * 16 + a_row_l;
                    int col = ks * 16 + a_koff;
                    ldsm_x4(afr[mt], sa + SWZ(row * 128 + col * 2));
                }
                uint32_t bfr[4][4];
                #pragma unroll
                for (int h = 0; h < 4; ++h) {
                    int row = warp_n * 64 + h * 16 + b_row_l;
                    int col = ks * 16 + b_koff;
                    ldsm_x4(bfr[h], sb + SWZ(row * 128 + col * 2));
                }
                #pragma unroll
                for (int mt = 0; mt < 4; ++mt)
                    #pragma unroll
                    for (int nt = 0; nt < 8; ++nt)
                        mma16816(acc[mt][nt], afr[mt],
                                 bfr[nt >> 1][(nt & 1) * 2], bfr[nt >> 1][(nt & 1) * 2 + 1]);
            }
            CP_COMMIT();
        }

        __syncthreads();                 // compute done; s_tile visible
        const int tn = s_tile;

        int bm2 = 0, bn2 = 0;
        const __half *Ab2 = nullptr, *Bb2 = nullptr;
        if (tn < NTILES) {
            map_tile(tn, Ab2, Bb2, bm2, bn2);
            fill_full(sbase, 0, 0, Ab2, Bb2, tid); CP_COMMIT();
            fill_full(sbase, 1, 1, Ab2, Bb2, tid); CP_COMMIT();
            fill_full(sbase, 2, 2, Ab2, Bb2, tid); CP_COMMIT();
        }

        {
            const int gr = lane >> 2;
            const int gc = (lane & 3) * 2;
            #pragma unroll
            for (int mt = 0; mt < 4; ++mt) {
                int row0 = bm * BM + warp_m * 64 + mt * 16 + gr;
                #pragma unroll
                for (int nt = 0; nt < 8; ++nt) {
                    int col = bn * BN + warp_n * 64 + nt * 8 + gc;
                    float2 b2 = *reinterpret_cast<const float2*>(bias + col);
                    stcs_f2(out + (size_t)row0 * OUTF + col,
                            acc[mt][nt][0] + b2.x, acc[mt][nt][1] + b2.y);
                    stcs_f2(out + (size_t)(row0 + 8) * OUTF + col,
                            acc[mt][nt][2] + b2.x, acc[mt][nt][3] + b2.y);
                    acc[mt][nt][0] = 0.f; acc[mt][nt][1] = 0.f;
                    acc[mt][nt][2] = 0.f; acc[mt][nt][3] = 0.f;
                }
            }
        }

        if (tn >= NTILES) break;
        t = tn; bm = bm2; bn = bn2; Ab = Ab2; Bb = Bb2;
    }
}

// ---------------- launch ----------------
extern "C" void kernel_launch(void* const* d_in, const int* in_sizes, int n_in,
                              void* d_out, int out_size) {
    const float* x    = (const float*)d_in[0];
    const float* w    = (const float*)d_in[1];
    const float* bias = (const float*)d_in[2];
    const int*   ridx = (const int*)d_in[3];
    const int*   cidx = (const int*)d_in[4];
    float* out = (float*)d_out;
    const int nnz = in_sizes[1];

    cudaFuncSetAttribute(gemm_kernel, cudaFuncAttributeMaxDynamicSharedMemorySize, SMEM_DYN);

    zero_tag<<<2048, 256>>>();
    scatter_cvt<<<2048, 256>>>(ridx, cidx, x, nnz);
    build_w<<<2048, 256>>>(w);

    // 148 workers (occ=1): surplus CTAs would only launch-and-exit
    gemm_kernel<<<148, 256, SMEM_DYN>>>(bias, out);
}